// round 9
// baseline (speedup 1.0000x reference)
#include <cuda_runtime.h>
#include <math.h>

// Problem constants: B=4, n=4096 points, m=512 triangles.
#define BATCH 4
#define NPTS  4096
#define MTRI  512
#define BN    (BATCH * NPTS)   // 16384

// Decomposition: 64-thread CTAs, 16 points/CTA, grid = 1024.
//   chunk = tid & 31 (32 triangle chunks), quad = tid >> 5 (2 quads).
//   Each thread: 8 points x 16 triangles (t = j*32 + chunk).
// 8 independent point-evals per thread supply ILP (j-loop NOT unrolled, keeps
// regs ~90 < 102 budget of __launch_bounds__(64,10) -> 10 CTAs/SM -> the whole
// 1024-CTA grid is resident in ONE wave (capacity 1480), ~1% imbalance.
// Total staging cost identical to round 7 (same 1024 CTAs x 512 triangles).
//
// Candidate-min formulation:
//   dist^2 = min(seg_ab, seg_ac, seg_bc, inside ? face : +inf)
// Explicit difference vectors (no cancellation). Region code recomputed
// reference-exactly for the winning triangle only.

__device__ __forceinline__ float frcp(float x) {
    float r;
    asm("rcp.approx.f32 %0, %1;" : "=f"(r) : "f"(x));
    return r;
}

__device__ int region_of(float px, float py, float pz,
                         float ax, float ay, float az,
                         float bx, float by, float bz,
                         float cx, float cy, float cz)
{
    const float abx = bx - ax, aby = by - ay, abz = bz - az;
    const float acx = cx - ax, acy = cy - ay, acz = cz - az;
    const float apx = px - ax, apy = py - ay, apz = pz - az;
    const float bpx = px - bx, bpy = py - by, bpz = pz - bz;
    const float cpx = px - cx, cpy = py - cy, cpz = pz - cz;
    const float d1 = abx * apx + aby * apy + abz * apz;
    const float d2 = acx * apx + acy * apy + acz * apz;
    const float d3 = abx * bpx + aby * bpy + abz * bpz;
    const float d4 = acx * bpx + acy * bpy + acz * bpz;
    const float d5 = abx * cpx + aby * cpy + abz * cpz;
    const float d6 = acx * cpx + acy * cpy + acz * cpz;
    const float vc = d1 * d4 - d3 * d2;
    const float vb = d5 * d2 - d1 * d6;
    const float va = d3 * d6 - d5 * d4;
    if (d1 <= 0.f && d2 <= 0.f) return 0;
    if (d3 >= 0.f && d4 <= d3) return 1;
    if (vc <= 0.f && d1 >= 0.f && d3 <= 0.f) return 3;
    if (d6 >= 0.f && d5 <= d6) return 2;
    if (vb <= 0.f && d2 >= 0.f && d6 <= 0.f) return 4;
    if (va <= 0.f && (d4 - d3) >= 0.f && (d5 - d6) >= 0.f) return 5;
    return 6;
}

__global__ void __launch_bounds__(64, 10)
tridist_kernel(const float* __restrict__ xyz,
               const float* __restrict__ tri1,
               const float* __restrict__ tri2,
               const float* __restrict__ tri3,
               float* __restrict__ out)
{
    __shared__ float sm[9][MTRI];   // ax ay az bx by bz cx cy cz  (SoA)
    __shared__ float sp[48];        // 16 points * 3

    const int b     = blockIdx.x >> 8;
    const int blk   = blockIdx.x & 255;
    const int pbase = b * NPTS + blk * 16;

    // Stage triangles (float4 loads, SoA scatter into smem).
    {
        const float4* t1 = (const float4*)(tri1 + b * MTRI * 3);
        const float4* t2 = (const float4*)(tri2 + b * MTRI * 3);
        const float4* t3 = (const float4*)(tri3 + b * MTRI * 3);
        #pragma unroll
        for (int it = 0; it < 6; ++it) {
            const int i4 = it * 64 + threadIdx.x;    // 0..383
            float4 v1 = t1[i4], v2 = t2[i4], v3 = t3[i4];
            const int base = i4 * 4;
            float f1[4] = {v1.x, v1.y, v1.z, v1.w};
            float f2[4] = {v2.x, v2.y, v2.z, v2.w};
            float f3[4] = {v3.x, v3.y, v3.z, v3.w};
            #pragma unroll
            for (int e = 0; e < 4; ++e) {
                const int idx = base + e;
                const int j = idx / 3;
                const int k = idx - j * 3;
                sm[k    ][j] = f1[e];
                sm[3 + k][j] = f2[e];
                sm[6 + k][j] = f3[e];
            }
        }
        if (threadIdx.x < 48) sp[threadIdx.x] = xyz[pbase * 3 + threadIdx.x];
    }
    __syncthreads();

    const int chunk = threadIdx.x & 31;
    const int quad  = threadIdx.x >> 5;   // 0..1, 8 points each

    float px[8], py[8], pz[8];
    float bestD[8];
    int   bestT[8];
    #pragma unroll
    for (int k = 0; k < 8; ++k) {
        px[k] = sp[(quad * 8 + k) * 3 + 0];
        py[k] = sp[(quad * 8 + k) * 3 + 1];
        pz[k] = sp[(quad * 8 + k) * 3 + 2];
        bestD[k] = INFINITY;
        bestT[k] = 0x7fffffff;
    }

    #pragma unroll 1
    for (int j = 0; j < 16; ++j) {
        const int t = j * 32 + chunk;

        const float ax = sm[0][t], ay = sm[1][t], az = sm[2][t];
        const float bx = sm[3][t], by = sm[4][t], bz = sm[5][t];
        const float cx = sm[6][t], cy = sm[7][t], cz = sm[8][t];

        // Per-triangle setup, amortized over 8 points.
        const float abx = bx - ax, aby = by - ay, abz = bz - az;
        const float acx = cx - ax, acy = cy - ay, acz = cz - az;
        const float cbx = cx - bx, cby = cy - by, cbz = cz - bz;
        const float e1 = fmaf(abx, abx, fmaf(aby, aby, abz * abz));
        const float e2 = fmaf(abx, acx, fmaf(aby, acy, abz * acz));
        const float e3 = fmaf(acx, acx, fmaf(acy, acy, acz * acz));
        const float cb2 = fmaf(cbx, cbx, fmaf(cby, cby, cbz * cbz));
        const float f1  = e1 - e2;                      // for u1 = (d2-d1)+f1
        const float denom = fmaf(e1, e3, -(e2 * e2));   // |ab x ac|^2
        const float r_e1 = frcp(e1);
        const float r_e3 = frcp(e3);
        const float r_cb = frcp(cb2);
        const float r_dn = frcp(denom);

        #pragma unroll
        for (int k = 0; k < 8; ++k) {
            const float apx = px[k] - ax, apy = py[k] - ay, apz = pz[k] - az;
            const float d1 = fmaf(abx, apx, fmaf(aby, apy, abz * apz));
            const float d2 = fmaf(acx, apx, fmaf(acy, apy, acz * apz));

            // --- segment AB ---
            const float tA = fminf(fmaxf(d1 * r_e1, 0.f), 1.f);
            const float ax1 = fmaf(-tA, abx, apx);
            const float ay1 = fmaf(-tA, aby, apy);
            const float az1 = fmaf(-tA, abz, apz);
            const float dAB = fmaf(ax1, ax1, fmaf(ay1, ay1, az1 * az1));

            // --- segment AC ---
            const float tC = fminf(fmaxf(d2 * r_e3, 0.f), 1.f);
            const float cx1 = fmaf(-tC, acx, apx);
            const float cy1 = fmaf(-tC, acy, apy);
            const float cz1 = fmaf(-tC, acz, apz);
            const float dAC = fmaf(cx1, cx1, fmaf(cy1, cy1, cz1 * cz1));

            // --- segment BC ---  (bp = ap - ab; u1 = (d2-d1)+f1 = cb.bp)
            const float bpx = apx - abx, bpy = apy - aby, bpz = apz - abz;
            const float u1 = (d2 - d1) + f1;
            const float tB = fminf(fmaxf(u1 * r_cb, 0.f), 1.f);
            const float bx1 = fmaf(-tB, cbx, bpx);
            const float by1 = fmaf(-tB, cby, bpy);
            const float bz1 = fmaf(-tB, cbz, bpz);
            const float dBC = fmaf(bx1, bx1, fmaf(by1, by1, bz1 * bz1));

            // --- face (valid only if projection inside) ---
            const float vb = fmaf(e3, d1, -(e2 * d2));
            const float vc = fmaf(e1, d2, -(e2 * d1));
            const float va = denom - vb - vc;
            const float v = vb * r_dn;
            const float w = vc * r_dn;
            const float fx1 = fmaf(-w, acx, fmaf(-v, abx, apx));
            const float fy1 = fmaf(-w, acy, fmaf(-v, aby, apy));
            const float fz1 = fmaf(-w, acz, fmaf(-v, abz, apz));
            const float dF  = fmaf(fx1, fx1, fmaf(fy1, fy1, fz1 * fz1));
            const float s   = fminf(fminf(va, vb), vc);
            const float dFc = (s >= 0.f) ? dF : INFINITY;  // NaN -> excluded

            const float d2s = fminf(fminf(fminf(dAB, dAC), dBC), dFc);

            if (d2s < bestD[k]) {   // t strictly increases -> first-win ok
                bestD[k] = d2s;
                bestT[k] = t;
            }
        }
    }

    // Lexicographic (dist, index) butterfly reduction across the 32 chunks.
    #pragma unroll
    for (int off = 1; off < 32; off <<= 1) {
        #pragma unroll
        for (int k = 0; k < 8; ++k) {
            float dO = __shfl_xor_sync(0xffffffffu, bestD[k], off);
            int   tO = __shfl_xor_sync(0xffffffffu, bestT[k], off);
            if (dO < bestD[k] || (dO == bestD[k] && tO < bestT[k])) {
                bestD[k] = dO;
                bestT[k] = tO;
            }
        }
    }

    if (chunk == 0) {
        #pragma unroll
        for (int k = 0; k < 8; ++k) {
            const int g = pbase + quad * 8 + k;
            const int t = bestT[k];
            const int r = region_of(px[k], py[k], pz[k],
                                    sm[0][t], sm[1][t], sm[2][t],
                                    sm[3][t], sm[4][t], sm[5][t],
                                    sm[6][t], sm[7][t], sm[8][t]);
            out[g]          = bestD[k];
            out[BN + g]     = (float)r;
            out[2 * BN + g] = (float)t;
        }
    }
}

extern "C" void kernel_launch(void* const* d_in, const int* in_sizes, int n_in,
                              void* d_out, int out_size)
{
    const float* xyz  = (const float*)d_in[0];
    const float* tri1 = (const float*)d_in[1];
    const float* tri2 = (const float*)d_in[2];
    const float* tri3 = (const float*)d_in[3];
    float* out = (float*)d_out;

    dim3 grid(BN / 16);   // 1024 CTAs
    dim3 block(64);
    tridist_kernel<<<grid, block>>>(xyz, tri1, tri2, tri3, out);
}

// round 10
// speedup vs baseline: 1.0891x; 1.0891x over previous
#include <cuda_runtime.h>
#include <math.h>

// Problem constants: B=4, n=4096 points, m=512 triangles.
#define BATCH 4
#define NPTS  4096
#define MTRI  512
#define BN    (BATCH * NPTS)   // 16384

// Decomposition: 64-thread CTAs, 16 points/CTA, grid = 1024.
//   chunk = tid & 31 (32 triangle chunks), quad = tid >> 5 (2 groups).
//   Each thread: 8 points = 4 packed f32x2 PAIRS x 16 triangles.
// __launch_bounds__(64,8): 128-reg budget -> 8 CTAs/SM -> whole grid in one
// wave (capacity 1184 >= 1024).
//
// Packed-pair candidate-min evaluation:
//   dist^2 = min(seg_ab, seg_ac, seg_bc, inside ? face : +inf)
// computed with fma.rn.f32x2 / mul.rn.f32x2 / add.rn.f32x2 (SASS FFMA2 path,
// 2 points per instruction). Per-component IEEE rounding == scalar version.
// Subtraction/negation via packed (-1,-1) and negated reciprocals:
//   tn = clamp(d * (-rcp), -1, 0);  diff = ap + tn*edge  (== ap - t*edge).
// Region code recomputed reference-exactly for the winning triangle only.

typedef unsigned long long ull;

__device__ __forceinline__ ull pk2(float lo, float hi) {
    ull r;
    asm("mov.b64 %0, {%1, %2};" : "=l"(r) : "f"(lo), "f"(hi));
    return r;
}
__device__ __forceinline__ void up2(ull v, float& lo, float& hi) {
    asm("mov.b64 {%0, %1}, %2;" : "=f"(lo), "=f"(hi) : "l"(v));
}
__device__ __forceinline__ ull fma2_(ull a, ull b, ull c) {
    ull r;
    asm("fma.rn.f32x2 %0, %1, %2, %3;" : "=l"(r) : "l"(a), "l"(b), "l"(c));
    return r;
}
__device__ __forceinline__ ull mul2_(ull a, ull b) {
    ull r;
    asm("mul.rn.f32x2 %0, %1, %2;" : "=l"(r) : "l"(a), "l"(b));
    return r;
}
__device__ __forceinline__ ull add2_(ull a, ull b) {
    ull r;
    asm("add.rn.f32x2 %0, %1, %2;" : "=l"(r) : "l"(a), "l"(b));
    return r;
}
__device__ __forceinline__ float frcp(float x) {
    float r;
    asm("rcp.approx.f32 %0, %1;" : "=f"(r) : "f"(x));
    return r;
}
// clamp both components of a packed value to [-1, 0]
__device__ __forceinline__ ull clampn2(ull v) {
    float lo, hi;
    up2(v, lo, hi);
    lo = fminf(fmaxf(lo, -1.f), 0.f);
    hi = fminf(fmaxf(hi, -1.f), 0.f);
    return pk2(lo, hi);
}

__device__ int region_of(float px, float py, float pz,
                         float ax, float ay, float az,
                         float bx, float by, float bz,
                         float cx, float cy, float cz)
{
    const float abx = bx - ax, aby = by - ay, abz = bz - az;
    const float acx = cx - ax, acy = cy - ay, acz = cz - az;
    const float apx = px - ax, apy = py - ay, apz = pz - az;
    const float bpx = px - bx, bpy = py - by, bpz = pz - bz;
    const float cpx = px - cx, cpy = py - cy, cpz = pz - cz;
    const float d1 = abx * apx + aby * apy + abz * apz;
    const float d2 = acx * apx + acy * apy + acz * apz;
    const float d3 = abx * bpx + aby * bpy + abz * bpz;
    const float d4 = acx * bpx + acy * bpy + acz * bpz;
    const float d5 = abx * cpx + aby * cpy + abz * cpz;
    const float d6 = acx * cpx + acy * cpy + acz * cpz;
    const float vc = d1 * d4 - d3 * d2;
    const float vb = d5 * d2 - d1 * d6;
    const float va = d3 * d6 - d5 * d4;
    if (d1 <= 0.f && d2 <= 0.f) return 0;
    if (d3 >= 0.f && d4 <= d3) return 1;
    if (vc <= 0.f && d1 >= 0.f && d3 <= 0.f) return 3;
    if (d6 >= 0.f && d5 <= d6) return 2;
    if (vb <= 0.f && d2 >= 0.f && d6 <= 0.f) return 4;
    if (va <= 0.f && (d4 - d3) >= 0.f && (d5 - d6) >= 0.f) return 5;
    return 6;
}

__global__ void __launch_bounds__(64, 8)
tridist_kernel(const float* __restrict__ xyz,
               const float* __restrict__ tri1,
               const float* __restrict__ tri2,
               const float* __restrict__ tri3,
               float* __restrict__ out)
{
    __shared__ float sm[9][MTRI];   // ax ay az bx by bz cx cy cz  (SoA)
    __shared__ float sp[48];        // 16 points * 3

    const int b     = blockIdx.x >> 8;
    const int blk   = blockIdx.x & 255;
    const int pbase = b * NPTS + blk * 16;

    // Stage triangles (float4 loads, SoA scatter into smem).
    {
        const float4* t1 = (const float4*)(tri1 + b * MTRI * 3);
        const float4* t2 = (const float4*)(tri2 + b * MTRI * 3);
        const float4* t3 = (const float4*)(tri3 + b * MTRI * 3);
        #pragma unroll
        for (int it = 0; it < 6; ++it) {
            const int i4 = it * 64 + threadIdx.x;    // 0..383
            float4 v1 = t1[i4], v2 = t2[i4], v3 = t3[i4];
            const int base = i4 * 4;
            float f1[4] = {v1.x, v1.y, v1.z, v1.w};
            float f2[4] = {v2.x, v2.y, v2.z, v2.w};
            float f3[4] = {v3.x, v3.y, v3.z, v3.w};
            #pragma unroll
            for (int e = 0; e < 4; ++e) {
                const int idx = base + e;
                const int j = idx / 3;
                const int k = idx - j * 3;
                sm[k    ][j] = f1[e];
                sm[3 + k][j] = f2[e];
                sm[6 + k][j] = f3[e];
            }
        }
        if (threadIdx.x < 48) sp[threadIdx.x] = xyz[pbase * 3 + threadIdx.x];
    }
    __syncthreads();

    const int chunk = threadIdx.x & 31;
    const int quad  = threadIdx.x >> 5;   // 0..1, 8 points each

    // 4 packed point pairs
    ull PPX[4], PPY[4], PPZ[4];
    float bestD[8];
    int   bestT[8];
    #pragma unroll
    for (int pr = 0; pr < 4; ++pr) {
        const int p0 = (quad * 8 + 2 * pr) * 3;
        PPX[pr] = pk2(sp[p0 + 0], sp[p0 + 3]);
        PPY[pr] = pk2(sp[p0 + 1], sp[p0 + 4]);
        PPZ[pr] = pk2(sp[p0 + 2], sp[p0 + 5]);
    }
    #pragma unroll
    for (int k = 0; k < 8; ++k) { bestD[k] = INFINITY; bestT[k] = 0x7fffffff; }

    const ull N1 = pk2(-1.f, -1.f);

    #pragma unroll 1
    for (int j = 0; j < 16; ++j) {
        const int t = j * 32 + chunk;

        const float ax = sm[0][t], ay = sm[1][t], az = sm[2][t];
        const float bx = sm[3][t], by = sm[4][t], bz = sm[5][t];
        const float cx = sm[6][t], cy = sm[7][t], cz = sm[8][t];

        // scalar per-triangle setup
        const float abx = bx - ax, aby = by - ay, abz = bz - az;
        const float acx = cx - ax, acy = cy - ay, acz = cz - az;
        const float cbx = cx - bx, cby = cy - by, cbz = cz - bz;
        const float e1 = fmaf(abx, abx, fmaf(aby, aby, abz * abz));
        const float e2 = fmaf(abx, acx, fmaf(aby, acy, abz * acz));
        const float e3 = fmaf(acx, acx, fmaf(acy, acy, acz * acz));
        const float f1s = e1 - e2;
        const float f2s = e3 - e2;
        const float cb2 = f1s + f2s;                    // |cb|^2
        const float denom = fmaf(e1, e3, -(e2 * e2));   // |ab x ac|^2
        const float nre1 = -frcp(e1);
        const float nre3 = -frcp(e3);
        const float nrcb = -frcp(cb2);
        const float nrdn = -frcp(denom);

        // packed broadcast constants (amortized over 4 pairs)
        const ull NAX = pk2(-ax, -ax), NAY = pk2(-ay, -ay), NAZ = pk2(-az, -az);
        const ull ABX = pk2(abx, abx), ABY = pk2(aby, aby), ABZ = pk2(abz, abz);
        const ull ACX = pk2(acx, acx), ACY = pk2(acy, acy), ACZ = pk2(acz, acz);
        const ull CBX = pk2(cbx, cbx), CBY = pk2(cby, cby), CBZ = pk2(cbz, cbz);
        const ull E1P = pk2(e1, e1), E2P = pk2(e2, e2), E3P = pk2(e3, e3);
        const ull F1P = pk2(f1s, f1s), DNP = pk2(denom, denom);
        const ull NRE1 = pk2(nre1, nre1), NRE3 = pk2(nre3, nre3);
        const ull NRCB = pk2(nrcb, nrcb), NRDN = pk2(nrdn, nrdn);

        #pragma unroll
        for (int pr = 0; pr < 4; ++pr) {
            const ull APX = add2_(PPX[pr], NAX);
            const ull APY = add2_(PPY[pr], NAY);
            const ull APZ = add2_(PPZ[pr], NAZ);

            const ull D1 = fma2_(ABX, APX, fma2_(ABY, APY, mul2_(ABZ, APZ)));
            const ull D2 = fma2_(ACX, APX, fma2_(ACY, APY, mul2_(ACZ, APZ)));

            // --- segment AB ---  tn = clamp(d1*(-1/e1), -1, 0)
            ull TN = clampn2(mul2_(D1, NRE1));
            ull DX = fma2_(ABX, TN, APX);
            ull DY = fma2_(ABY, TN, APY);
            ull DZ = fma2_(ABZ, TN, APZ);
            const ull DAB = fma2_(DX, DX, fma2_(DY, DY, mul2_(DZ, DZ)));

            // --- segment AC ---
            TN = clampn2(mul2_(D2, NRE3));
            DX = fma2_(ACX, TN, APX);
            DY = fma2_(ACY, TN, APY);
            DZ = fma2_(ACZ, TN, APZ);
            const ull DAC = fma2_(DX, DX, fma2_(DY, DY, mul2_(DZ, DZ)));

            // --- segment BC ---  bp = ap - ab; u1 = (d2-d1)+f1
            const ull BPX = fma2_(ABX, N1, APX);
            const ull BPY = fma2_(ABY, N1, APY);
            const ull BPZ = fma2_(ABZ, N1, APZ);
            const ull U1 = add2_(fma2_(D1, N1, D2), F1P);
            TN = clampn2(mul2_(U1, NRCB));
            DX = fma2_(CBX, TN, BPX);
            DY = fma2_(CBY, TN, BPY);
            DZ = fma2_(CBZ, TN, BPZ);
            const ull DBC = fma2_(DX, DX, fma2_(DY, DY, mul2_(DZ, DZ)));

            // --- face ---  vb = e3*d1 - e2*d2 ; vc = e1*d2 - e2*d1
            const ull VB = fma2_(mul2_(E2P, D2), N1, mul2_(E3P, D1));
            const ull VC = fma2_(mul2_(E2P, D1), N1, mul2_(E1P, D2));
            ull VA = fma2_(VB, N1, DNP);
            VA = fma2_(VC, N1, VA);
            const ull NV = mul2_(VB, NRDN);   // = -v
            const ull NW = mul2_(VC, NRDN);   // = -w
            DX = fma2_(ABX, NV, fma2_(ACX, NW, APX));
            DY = fma2_(ABY, NV, fma2_(ACY, NW, APY));
            DZ = fma2_(ABZ, NV, fma2_(ACZ, NW, APZ));
            const ull DF = fma2_(DX, DX, fma2_(DY, DY, mul2_(DZ, DZ)));

            // --- per-component resolve ---
            float va0, va1, vb0, vb1, vc0, vc1, df0, df1;
            float a0, a1, c0, c1, b0, b1;
            up2(VA, va0, va1); up2(VB, vb0, vb1); up2(VC, vc0, vc1);
            up2(DF, df0, df1);
            up2(DAB, a0, a1); up2(DAC, c0, c1); up2(DBC, b0, b1);

            const float s0 = fminf(fminf(va0, vb0), vc0);
            const float s1 = fminf(fminf(va1, vb1), vc1);
            float d0 = fminf(fminf(a0, c0), b0);
            float d1v = fminf(fminf(a1, c1), b1);
            if (s0 >= 0.f) d0  = fminf(d0,  df0);   // NaN s -> skip face
            if (s1 >= 0.f) d1v = fminf(d1v, df1);

            const int k0 = 2 * pr;
            if (d0  < bestD[k0])     { bestD[k0]     = d0;  bestT[k0]     = t; }
            if (d1v < bestD[k0 + 1]) { bestD[k0 + 1] = d1v; bestT[k0 + 1] = t; }
        }
    }

    // Lexicographic (dist, index) butterfly reduction across the 32 chunks.
    #pragma unroll
    for (int off = 1; off < 32; off <<= 1) {
        #pragma unroll
        for (int k = 0; k < 8; ++k) {
            float dO = __shfl_xor_sync(0xffffffffu, bestD[k], off);
            int   tO = __shfl_xor_sync(0xffffffffu, bestT[k], off);
            if (dO < bestD[k] || (dO == bestD[k] && tO < bestT[k])) {
                bestD[k] = dO;
                bestT[k] = tO;
            }
        }
    }

    if (chunk == 0) {
        #pragma unroll
        for (int k = 0; k < 8; ++k) {
            const int g = pbase + quad * 8 + k;
            const int t = bestT[k];
            const float px = sp[(quad * 8 + k) * 3 + 0];
            const float py = sp[(quad * 8 + k) * 3 + 1];
            const float pz = sp[(quad * 8 + k) * 3 + 2];
            const int r = region_of(px, py, pz,
                                    sm[0][t], sm[1][t], sm[2][t],
                                    sm[3][t], sm[4][t], sm[5][t],
                                    sm[6][t], sm[7][t], sm[8][t]);
            out[g]          = bestD[k];
            out[BN + g]     = (float)r;
            out[2 * BN + g] = (float)t;
        }
    }
}

extern "C" void kernel_launch(void* const* d_in, const int* in_sizes, int n_in,
                              void* d_out, int out_size)
{
    const float* xyz  = (const float*)d_in[0];
    const float* tri1 = (const float*)d_in[1];
    const float* tri2 = (const float*)d_in[2];
    const float* tri3 = (const float*)d_in[3];
    float* out = (float*)d_out;

    dim3 grid(BN / 16);   // 1024 CTAs
    dim3 block(64);
    tridist_kernel<<<grid, block>>>(xyz, tri1, tri2, tri3, out);
}

// round 11
// speedup vs baseline: 1.0963x; 1.0066x over previous
#include <cuda_runtime.h>
#include <math.h>

// Problem constants: B=4, n=4096 points, m=512 triangles.
#define BATCH 4
#define NPTS  4096
#define MTRI  512
#define BN    (BATCH * NPTS)   // 16384

// Decomposition: 64-thread CTAs, 16 points/CTA, grid = 1024.
//   chunk = tid & 31 (32 triangle chunks), quad = tid >> 5 (2 groups).
//   Each thread: 8 points = 4 packed f32x2 pairs x 16 triangles.
// __launch_bounds__(64,9): 113-reg budget -> 9 CTAs/SM, 18 warps/SM, whole
// grid resident in one wave (capacity 1332 >= 1024).
//
// Packed-pair candidate-min evaluation (fma.rn.f32x2 path):
//   dist^2 = min(seg_ab, seg_ac, seg_bc, inside ? face : +inf)
// Register cuts vs the previous version:
//  - BC segment on the a-origin: diff = ap + TN*ac + TM*ab, TM = -1-TN
//    (no packed cb constants).
//  - face: -v = d1*q1 + d2*q2, -w = d2*q3 + d1*q2 with scalar pre-divided
//    q1=-e3/dn, q2=e2/dn, q3=-e1/dn; inside <=> max(-v,-w)<=0 && (-v-w)>=-1.
// Region code recomputed reference-exactly for the winning triangle only.

typedef unsigned long long ull;

__device__ __forceinline__ ull pk2(float lo, float hi) {
    ull r;
    asm("mov.b64 %0, {%1, %2};" : "=l"(r) : "f"(lo), "f"(hi));
    return r;
}
__device__ __forceinline__ void up2(ull v, float& lo, float& hi) {
    asm("mov.b64 {%0, %1}, %2;" : "=f"(lo), "=f"(hi) : "l"(v));
}
__device__ __forceinline__ ull fma2_(ull a, ull b, ull c) {
    ull r;
    asm("fma.rn.f32x2 %0, %1, %2, %3;" : "=l"(r) : "l"(a), "l"(b), "l"(c));
    return r;
}
__device__ __forceinline__ ull mul2_(ull a, ull b) {
    ull r;
    asm("mul.rn.f32x2 %0, %1, %2;" : "=l"(r) : "l"(a), "l"(b));
    return r;
}
__device__ __forceinline__ ull add2_(ull a, ull b) {
    ull r;
    asm("add.rn.f32x2 %0, %1, %2;" : "=l"(r) : "l"(a), "l"(b));
    return r;
}
__device__ __forceinline__ float frcp(float x) {
    float r;
    asm("rcp.approx.f32 %0, %1;" : "=f"(r) : "f"(x));
    return r;
}
// clamp both components of a packed value to [-1, 0]
__device__ __forceinline__ ull clampn2(ull v) {
    float lo, hi;
    up2(v, lo, hi);
    lo = fminf(fmaxf(lo, -1.f), 0.f);
    hi = fminf(fmaxf(hi, -1.f), 0.f);
    return pk2(lo, hi);
}

__device__ int region_of(float px, float py, float pz,
                         float ax, float ay, float az,
                         float bx, float by, float bz,
                         float cx, float cy, float cz)
{
    const float abx = bx - ax, aby = by - ay, abz = bz - az;
    const float acx = cx - ax, acy = cy - ay, acz = cz - az;
    const float apx = px - ax, apy = py - ay, apz = pz - az;
    const float bpx = px - bx, bpy = py - by, bpz = pz - bz;
    const float cpx = px - cx, cpy = py - cy, cpz = pz - cz;
    const float d1 = abx * apx + aby * apy + abz * apz;
    const float d2 = acx * apx + acy * apy + acz * apz;
    const float d3 = abx * bpx + aby * bpy + abz * bpz;
    const float d4 = acx * bpx + acy * bpy + acz * bpz;
    const float d5 = abx * cpx + aby * cpy + abz * cpz;
    const float d6 = acx * cpx + acy * cpy + acz * cpz;
    const float vc = d1 * d4 - d3 * d2;
    const float vb = d5 * d2 - d1 * d6;
    const float va = d3 * d6 - d5 * d4;
    if (d1 <= 0.f && d2 <= 0.f) return 0;
    if (d3 >= 0.f && d4 <= d3) return 1;
    if (vc <= 0.f && d1 >= 0.f && d3 <= 0.f) return 3;
    if (d6 >= 0.f && d5 <= d6) return 2;
    if (vb <= 0.f && d2 >= 0.f && d6 <= 0.f) return 4;
    if (va <= 0.f && (d4 - d3) >= 0.f && (d5 - d6) >= 0.f) return 5;
    return 6;
}

__global__ void __launch_bounds__(64, 9)
tridist_kernel(const float* __restrict__ xyz,
               const float* __restrict__ tri1,
               const float* __restrict__ tri2,
               const float* __restrict__ tri3,
               float* __restrict__ out)
{
    __shared__ float sm[9][MTRI];   // ax ay az bx by bz cx cy cz  (SoA)
    __shared__ float sp[48];        // 16 points * 3

    const int b     = blockIdx.x >> 8;
    const int blk   = blockIdx.x & 255;
    const int pbase = b * NPTS + blk * 16;

    // Stage triangles (float4 loads, SoA scatter into smem).
    {
        const float4* t1 = (const float4*)(tri1 + b * MTRI * 3);
        const float4* t2 = (const float4*)(tri2 + b * MTRI * 3);
        const float4* t3 = (const float4*)(tri3 + b * MTRI * 3);
        #pragma unroll
        for (int it = 0; it < 6; ++it) {
            const int i4 = it * 64 + threadIdx.x;    // 0..383
            float4 v1 = t1[i4], v2 = t2[i4], v3 = t3[i4];
            const int base = i4 * 4;
            float f1[4] = {v1.x, v1.y, v1.z, v1.w};
            float f2[4] = {v2.x, v2.y, v2.z, v2.w};
            float f3[4] = {v3.x, v3.y, v3.z, v3.w};
            #pragma unroll
            for (int e = 0; e < 4; ++e) {
                const int idx = base + e;
                const int j = idx / 3;
                const int k = idx - j * 3;
                sm[k    ][j] = f1[e];
                sm[3 + k][j] = f2[e];
                sm[6 + k][j] = f3[e];
            }
        }
        if (threadIdx.x < 48) sp[threadIdx.x] = xyz[pbase * 3 + threadIdx.x];
    }
    __syncthreads();

    const int chunk = threadIdx.x & 31;
    const int quad  = threadIdx.x >> 5;   // 0..1, 8 points each

    // 4 packed point pairs
    ull PPX[4], PPY[4], PPZ[4];
    float bestD[8];
    int   bestT[8];
    #pragma unroll
    for (int pr = 0; pr < 4; ++pr) {
        const int p0 = (quad * 8 + 2 * pr) * 3;
        PPX[pr] = pk2(sp[p0 + 0], sp[p0 + 3]);
        PPY[pr] = pk2(sp[p0 + 1], sp[p0 + 4]);
        PPZ[pr] = pk2(sp[p0 + 2], sp[p0 + 5]);
    }
    #pragma unroll
    for (int k = 0; k < 8; ++k) { bestD[k] = INFINITY; bestT[k] = 0x7fffffff; }

    const ull N1 = pk2(-1.f, -1.f);

    #pragma unroll 1
    for (int j = 0; j < 16; ++j) {
        const int t = j * 32 + chunk;

        const float ax = sm[0][t], ay = sm[1][t], az = sm[2][t];
        const float bx = sm[3][t], by = sm[4][t], bz = sm[5][t];
        const float cx = sm[6][t], cy = sm[7][t], cz = sm[8][t];

        // scalar per-triangle setup
        const float abx = bx - ax, aby = by - ay, abz = bz - az;
        const float acx = cx - ax, acy = cy - ay, acz = cz - az;
        const float e1 = fmaf(abx, abx, fmaf(aby, aby, abz * abz));
        const float e2 = fmaf(abx, acx, fmaf(aby, acy, abz * acz));
        const float e3 = fmaf(acx, acx, fmaf(acy, acy, acz * acz));
        const float f1s = e1 - e2;
        const float f2s = e3 - e2;
        const float cb2 = f1s + f2s;                    // |cb|^2
        const float denom = fmaf(e1, e3, -(e2 * e2));   // |ab x ac|^2
        const float rdn  = frcp(denom);
        const float q1s  = -e3 * rdn;
        const float q2s  =  e2 * rdn;
        const float q3s  = -e1 * rdn;
        const float nre1 = -frcp(e1);
        const float nre3 = -frcp(e3);
        const float nrcb = -frcp(cb2);

        // 16 packed broadcast constants (amortized over 4 pairs)
        const ull NAX = pk2(-ax, -ax), NAY = pk2(-ay, -ay), NAZ = pk2(-az, -az);
        const ull ABX = pk2(abx, abx), ABY = pk2(aby, aby), ABZ = pk2(abz, abz);
        const ull ACX = pk2(acx, acx), ACY = pk2(acy, acy), ACZ = pk2(acz, acz);
        const ull F1P = pk2(f1s, f1s);
        const ull NRE1 = pk2(nre1, nre1), NRE3 = pk2(nre3, nre3);
        const ull NRCB = pk2(nrcb, nrcb);
        const ull Q1P = pk2(q1s, q1s), Q2P = pk2(q2s, q2s), Q3P = pk2(q3s, q3s);

        #pragma unroll
        for (int pr = 0; pr < 4; ++pr) {
            const ull APX = add2_(PPX[pr], NAX);
            const ull APY = add2_(PPY[pr], NAY);
            const ull APZ = add2_(PPZ[pr], NAZ);

            const ull D1 = fma2_(ABX, APX, fma2_(ABY, APY, mul2_(ABZ, APZ)));
            const ull D2 = fma2_(ACX, APX, fma2_(ACY, APY, mul2_(ACZ, APZ)));

            // --- segment AB ---  tn = clamp(d1*(-1/e1), -1, 0)
            ull TN = clampn2(mul2_(D1, NRE1));
            ull DX = fma2_(ABX, TN, APX);
            ull DY = fma2_(ABY, TN, APY);
            ull DZ = fma2_(ABZ, TN, APZ);
            const ull DAB = fma2_(DX, DX, fma2_(DY, DY, mul2_(DZ, DZ)));

            // --- segment AC ---
            TN = clampn2(mul2_(D2, NRE3));
            DX = fma2_(ACX, TN, APX);
            DY = fma2_(ACY, TN, APY);
            DZ = fma2_(ACZ, TN, APZ);
            const ull DAC = fma2_(DX, DX, fma2_(DY, DY, mul2_(DZ, DZ)));

            // --- segment BC ---  u1 = (d2-d1)+f1; a-origin form:
            //   diff = ap + TN*ac + TM*ab,  TM = -1 - TN
            const ull U1 = add2_(fma2_(D1, N1, D2), F1P);
            TN = clampn2(mul2_(U1, NRCB));
            const ull TM = fma2_(TN, N1, N1);
            DX = fma2_(ABX, TM, fma2_(ACX, TN, APX));
            DY = fma2_(ABY, TM, fma2_(ACY, TN, APY));
            DZ = fma2_(ABZ, TM, fma2_(ACZ, TN, APZ));
            const ull DBC = fma2_(DX, DX, fma2_(DY, DY, mul2_(DZ, DZ)));

            // --- face ---  nv = -v = d1*q1 + d2*q2 ; nw = -w = d2*q3 + d1*q2
            const ull NV = fma2_(D1, Q1P, mul2_(D2, Q2P));
            const ull NW = fma2_(D2, Q3P, mul2_(D1, Q2P));
            const ull SS = add2_(NV, NW);   // -(v+w)
            DX = fma2_(ABX, NV, fma2_(ACX, NW, APX));
            DY = fma2_(ABY, NV, fma2_(ACY, NW, APY));
            DZ = fma2_(ABZ, NV, fma2_(ACZ, NW, APZ));
            const ull DF = fma2_(DX, DX, fma2_(DY, DY, mul2_(DZ, DZ)));

            // --- per-component resolve ---
            float nv0, nv1, nw0, nw1, ss0, ss1, df0, df1;
            float a0, a1, c0, c1, b0, b1;
            up2(NV, nv0, nv1); up2(NW, nw0, nw1); up2(SS, ss0, ss1);
            up2(DF, df0, df1);
            up2(DAB, a0, a1); up2(DAC, c0, c1); up2(DBC, b0, b1);

            float d0  = fminf(fminf(a0, c0), b0);
            float d1v = fminf(fminf(a1, c1), b1);
            // inside <=> v>=0, w>=0, v+w<=1  <=> nv<=0, nw<=0, ss>=-1
            // (NaN -> comparisons false -> face excluded)
            if (fmaxf(nv0, nw0) <= 0.f && ss0 >= -1.f) d0  = fminf(d0,  df0);
            if (fmaxf(nv1, nw1) <= 0.f && ss1 >= -1.f) d1v = fminf(d1v, df1);

            const int k0 = 2 * pr;
            if (d0  < bestD[k0])     { bestD[k0]     = d0;  bestT[k0]     = t; }
            if (d1v < bestD[k0 + 1]) { bestD[k0 + 1] = d1v; bestT[k0 + 1] = t; }
        }
    }

    // Lexicographic (dist, index) butterfly reduction across the 32 chunks.
    #pragma unroll
    for (int off = 1; off < 32; off <<= 1) {
        #pragma unroll
        for (int k = 0; k < 8; ++k) {
            float dO = __shfl_xor_sync(0xffffffffu, bestD[k], off);
            int   tO = __shfl_xor_sync(0xffffffffu, bestT[k], off);
            if (dO < bestD[k] || (dO == bestD[k] && tO < bestT[k])) {
                bestD[k] = dO;
                bestT[k] = tO;
            }
        }
    }

    if (chunk == 0) {
        #pragma unroll
        for (int k = 0; k < 8; ++k) {
            const int g = pbase + quad * 8 + k;
            const int t = bestT[k];
            const float px = sp[(quad * 8 + k) * 3 + 0];
            const float py = sp[(quad * 8 + k) * 3 + 1];
            const float pz = sp[(quad * 8 + k) * 3 + 2];
            const int r = region_of(px, py, pz,
                                    sm[0][t], sm[1][t], sm[2][t],
                                    sm[3][t], sm[4][t], sm[5][t],
                                    sm[6][t], sm[7][t], sm[8][t]);
            out[g]          = bestD[k];
            out[BN + g]     = (float)r;
            out[2 * BN + g] = (float)t;
        }
    }
}

extern "C" void kernel_launch(void* const* d_in, const int* in_sizes, int n_in,
                              void* d_out, int out_size)
{
    const float* xyz  = (const float*)d_in[0];
    const float* tri1 = (const float*)d_in[1];
    const float* tri2 = (const float*)d_in[2];
    const float* tri3 = (const float*)d_in[3];
    float* out = (float*)d_out;

    dim3 grid(BN / 16);   // 1024 CTAs
    dim3 block(64);
    tridist_kernel<<<grid, block>>>(xyz, tri1, tri2, tri3, out);
}

// round 12
// speedup vs baseline: 1.1719x; 1.0690x over previous
#include <cuda_runtime.h>
#include <math.h>

// Problem constants: B=4, n=4096 points, m=512 triangles.
#define BATCH 4
#define NPTS  4096
#define MTRI  512
#define BN    (BATCH * NPTS)   // 16384

// Decomposition: 128-thread CTAs (4 warps), 16 points/CTA, grid = 1024.
//   chunk = tid & 31 (32 triangle chunks), grp = tid >> 5 (4 groups x 4 pts).
//   Each thread: 4 points = 2 packed f32x2 pairs x 16 triangles.
//   -> 4096 warps (~27.7/SM): covers the packed-FFMA2 dependency latency
//   (round 11: 14 warps/SM -> issue 56%; rounds 4/7 at this warp count: 75-79%).
//
// Packed-pair candidate-min evaluation (fma.rn.f32x2 path):
//   dist^2 = min(seg_ab, seg_ac, seg_bc, inside ? face : +inf)
//  - BC segment on the a-origin: diff = ap + TN*ac + TM*ab, TM = -1-TN.
//  - face: -v = d1*q1 + d2*q2, -w = d2*q3 + d1*q2 with scalar pre-divided
//    q1=-e3/dn, q2=e2/dn, q3=-e1/dn; inside <=> max(-v,-w)<=0 && -(v+w)>=-1.
// Region code recomputed reference-exactly for the winning triangle only.

typedef unsigned long long ull;

__device__ __forceinline__ ull pk2(float lo, float hi) {
    ull r;
    asm("mov.b64 %0, {%1, %2};" : "=l"(r) : "f"(lo), "f"(hi));
    return r;
}
__device__ __forceinline__ void up2(ull v, float& lo, float& hi) {
    asm("mov.b64 {%0, %1}, %2;" : "=f"(lo), "=f"(hi) : "l"(v));
}
__device__ __forceinline__ ull fma2_(ull a, ull b, ull c) {
    ull r;
    asm("fma.rn.f32x2 %0, %1, %2, %3;" : "=l"(r) : "l"(a), "l"(b), "l"(c));
    return r;
}
__device__ __forceinline__ ull mul2_(ull a, ull b) {
    ull r;
    asm("mul.rn.f32x2 %0, %1, %2;" : "=l"(r) : "l"(a), "l"(b));
    return r;
}
__device__ __forceinline__ ull add2_(ull a, ull b) {
    ull r;
    asm("add.rn.f32x2 %0, %1, %2;" : "=l"(r) : "l"(a), "l"(b));
    return r;
}
__device__ __forceinline__ float frcp(float x) {
    float r;
    asm("rcp.approx.f32 %0, %1;" : "=f"(r) : "f"(x));
    return r;
}
// clamp both components of a packed value to [-1, 0]
__device__ __forceinline__ ull clampn2(ull v) {
    float lo, hi;
    up2(v, lo, hi);
    lo = fminf(fmaxf(lo, -1.f), 0.f);
    hi = fminf(fmaxf(hi, -1.f), 0.f);
    return pk2(lo, hi);
}

__device__ int region_of(float px, float py, float pz,
                         float ax, float ay, float az,
                         float bx, float by, float bz,
                         float cx, float cy, float cz)
{
    const float abx = bx - ax, aby = by - ay, abz = bz - az;
    const float acx = cx - ax, acy = cy - ay, acz = cz - az;
    const float apx = px - ax, apy = py - ay, apz = pz - az;
    const float bpx = px - bx, bpy = py - by, bpz = pz - bz;
    const float cpx = px - cx, cpy = py - cy, cpz = pz - cz;
    const float d1 = abx * apx + aby * apy + abz * apz;
    const float d2 = acx * apx + acy * apy + acz * apz;
    const float d3 = abx * bpx + aby * bpy + abz * bpz;
    const float d4 = acx * bpx + acy * bpy + acz * bpz;
    const float d5 = abx * cpx + aby * cpy + abz * cpz;
    const float d6 = acx * cpx + acy * cpy + acz * cpz;
    const float vc = d1 * d4 - d3 * d2;
    const float vb = d5 * d2 - d1 * d6;
    const float va = d3 * d6 - d5 * d4;
    if (d1 <= 0.f && d2 <= 0.f) return 0;
    if (d3 >= 0.f && d4 <= d3) return 1;
    if (vc <= 0.f && d1 >= 0.f && d3 <= 0.f) return 3;
    if (d6 >= 0.f && d5 <= d6) return 2;
    if (vb <= 0.f && d2 >= 0.f && d6 <= 0.f) return 4;
    if (va <= 0.f && (d4 - d3) >= 0.f && (d5 - d6) >= 0.f) return 5;
    return 6;
}

__global__ void __launch_bounds__(128, 6)
tridist_kernel(const float* __restrict__ xyz,
               const float* __restrict__ tri1,
               const float* __restrict__ tri2,
               const float* __restrict__ tri3,
               float* __restrict__ out)
{
    __shared__ float sm[9][MTRI];   // ax ay az bx by bz cx cy cz  (SoA)
    __shared__ float sp[48];        // 16 points * 3

    const int b     = blockIdx.x >> 8;
    const int blk   = blockIdx.x & 255;
    const int pbase = b * NPTS + blk * 16;

    // Stage triangles (float4 loads, SoA scatter into smem).
    {
        const float4* t1 = (const float4*)(tri1 + b * MTRI * 3);
        const float4* t2 = (const float4*)(tri2 + b * MTRI * 3);
        const float4* t3 = (const float4*)(tri3 + b * MTRI * 3);
        #pragma unroll
        for (int it = 0; it < 3; ++it) {
            const int i4 = it * 128 + threadIdx.x;   // 0..383
            float4 v1 = t1[i4], v2 = t2[i4], v3 = t3[i4];
            const int base = i4 * 4;
            float f1[4] = {v1.x, v1.y, v1.z, v1.w};
            float f2[4] = {v2.x, v2.y, v2.z, v2.w};
            float f3[4] = {v3.x, v3.y, v3.z, v3.w};
            #pragma unroll
            for (int e = 0; e < 4; ++e) {
                const int idx = base + e;
                const int j = idx / 3;
                const int k = idx - j * 3;
                sm[k    ][j] = f1[e];
                sm[3 + k][j] = f2[e];
                sm[6 + k][j] = f3[e];
            }
        }
        if (threadIdx.x < 48) sp[threadIdx.x] = xyz[pbase * 3 + threadIdx.x];
    }
    __syncthreads();

    const int chunk = threadIdx.x & 31;
    const int grp   = threadIdx.x >> 5;   // 0..3, 4 points each

    // 2 packed point pairs
    ull PPX[2], PPY[2], PPZ[2];
    float bestD[4];
    int   bestT[4];
    #pragma unroll
    for (int pr = 0; pr < 2; ++pr) {
        const int p0 = (grp * 4 + 2 * pr) * 3;
        PPX[pr] = pk2(sp[p0 + 0], sp[p0 + 3]);
        PPY[pr] = pk2(sp[p0 + 1], sp[p0 + 4]);
        PPZ[pr] = pk2(sp[p0 + 2], sp[p0 + 5]);
    }
    #pragma unroll
    for (int k = 0; k < 4; ++k) { bestD[k] = INFINITY; bestT[k] = 0x7fffffff; }

    const ull N1 = pk2(-1.f, -1.f);

    #pragma unroll 1
    for (int j = 0; j < 16; ++j) {
        const int t = j * 32 + chunk;

        const float ax = sm[0][t], ay = sm[1][t], az = sm[2][t];
        const float bx = sm[3][t], by = sm[4][t], bz = sm[5][t];
        const float cx = sm[6][t], cy = sm[7][t], cz = sm[8][t];

        // scalar per-triangle setup
        const float abx = bx - ax, aby = by - ay, abz = bz - az;
        const float acx = cx - ax, acy = cy - ay, acz = cz - az;
        const float e1 = fmaf(abx, abx, fmaf(aby, aby, abz * abz));
        const float e2 = fmaf(abx, acx, fmaf(aby, acy, abz * acz));
        const float e3 = fmaf(acx, acx, fmaf(acy, acy, acz * acz));
        const float f1s = e1 - e2;
        const float f2s = e3 - e2;
        const float cb2 = f1s + f2s;                    // |cb|^2
        const float denom = fmaf(e1, e3, -(e2 * e2));   // |ab x ac|^2
        const float rdn  = frcp(denom);
        const float q1s  = -e3 * rdn;
        const float q2s  =  e2 * rdn;
        const float q3s  = -e1 * rdn;
        const float nre1 = -frcp(e1);
        const float nre3 = -frcp(e3);
        const float nrcb = -frcp(cb2);

        // 16 packed broadcast constants (amortized over 2 pairs)
        const ull NAX = pk2(-ax, -ax), NAY = pk2(-ay, -ay), NAZ = pk2(-az, -az);
        const ull ABX = pk2(abx, abx), ABY = pk2(aby, aby), ABZ = pk2(abz, abz);
        const ull ACX = pk2(acx, acx), ACY = pk2(acy, acy), ACZ = pk2(acz, acz);
        const ull F1P = pk2(f1s, f1s);
        const ull NRE1 = pk2(nre1, nre1), NRE3 = pk2(nre3, nre3);
        const ull NRCB = pk2(nrcb, nrcb);
        const ull Q1P = pk2(q1s, q1s), Q2P = pk2(q2s, q2s), Q3P = pk2(q3s, q3s);

        #pragma unroll
        for (int pr = 0; pr < 2; ++pr) {
            const ull APX = add2_(PPX[pr], NAX);
            const ull APY = add2_(PPY[pr], NAY);
            const ull APZ = add2_(PPZ[pr], NAZ);

            const ull D1 = fma2_(ABX, APX, fma2_(ABY, APY, mul2_(ABZ, APZ)));
            const ull D2 = fma2_(ACX, APX, fma2_(ACY, APY, mul2_(ACZ, APZ)));

            // --- segment AB ---  tn = clamp(d1*(-1/e1), -1, 0)
            ull TN = clampn2(mul2_(D1, NRE1));
            ull DX = fma2_(ABX, TN, APX);
            ull DY = fma2_(ABY, TN, APY);
            ull DZ = fma2_(ABZ, TN, APZ);
            const ull DAB = fma2_(DX, DX, fma2_(DY, DY, mul2_(DZ, DZ)));

            // --- segment AC ---
            TN = clampn2(mul2_(D2, NRE3));
            DX = fma2_(ACX, TN, APX);
            DY = fma2_(ACY, TN, APY);
            DZ = fma2_(ACZ, TN, APZ);
            const ull DAC = fma2_(DX, DX, fma2_(DY, DY, mul2_(DZ, DZ)));

            // --- segment BC ---  u1 = (d2-d1)+f1; a-origin form:
            //   diff = ap + TN*ac + TM*ab,  TM = -1 - TN
            const ull U1 = add2_(fma2_(D1, N1, D2), F1P);
            TN = clampn2(mul2_(U1, NRCB));
            const ull TM = fma2_(TN, N1, N1);
            DX = fma2_(ABX, TM, fma2_(ACX, TN, APX));
            DY = fma2_(ABY, TM, fma2_(ACY, TN, APY));
            DZ = fma2_(ABZ, TM, fma2_(ACZ, TN, APZ));
            const ull DBC = fma2_(DX, DX, fma2_(DY, DY, mul2_(DZ, DZ)));

            // --- face ---  nv = -v = d1*q1 + d2*q2 ; nw = -w = d2*q3 + d1*q2
            const ull NV = fma2_(D1, Q1P, mul2_(D2, Q2P));
            const ull NW = fma2_(D2, Q3P, mul2_(D1, Q2P));
            const ull SS = add2_(NV, NW);   // -(v+w)
            DX = fma2_(ABX, NV, fma2_(ACX, NW, APX));
            DY = fma2_(ABY, NV, fma2_(ACY, NW, APY));
            DZ = fma2_(ABZ, NV, fma2_(ACZ, NW, APZ));
            const ull DF = fma2_(DX, DX, fma2_(DY, DY, mul2_(DZ, DZ)));

            // --- per-component resolve ---
            float nv0, nv1, nw0, nw1, ss0, ss1, df0, df1;
            float a0, a1, c0, c1, b0, b1;
            up2(NV, nv0, nv1); up2(NW, nw0, nw1); up2(SS, ss0, ss1);
            up2(DF, df0, df1);
            up2(DAB, a0, a1); up2(DAC, c0, c1); up2(DBC, b0, b1);

            float d0  = fminf(fminf(a0, c0), b0);
            float d1v = fminf(fminf(a1, c1), b1);
            // inside <=> v>=0, w>=0, v+w<=1  <=> nv<=0, nw<=0, ss>=-1
            // (NaN -> comparisons false -> face excluded)
            if (fmaxf(nv0, nw0) <= 0.f && ss0 >= -1.f) d0  = fminf(d0,  df0);
            if (fmaxf(nv1, nw1) <= 0.f && ss1 >= -1.f) d1v = fminf(d1v, df1);

            const int k0 = 2 * pr;
            if (d0  < bestD[k0])     { bestD[k0]     = d0;  bestT[k0]     = t; }
            if (d1v < bestD[k0 + 1]) { bestD[k0 + 1] = d1v; bestT[k0 + 1] = t; }
        }
    }

    // Lexicographic (dist, index) butterfly reduction across the 32 chunks.
    #pragma unroll
    for (int off = 1; off < 32; off <<= 1) {
        #pragma unroll
        for (int k = 0; k < 4; ++k) {
            float dO = __shfl_xor_sync(0xffffffffu, bestD[k], off);
            int   tO = __shfl_xor_sync(0xffffffffu, bestT[k], off);
            if (dO < bestD[k] || (dO == bestD[k] && tO < bestT[k])) {
                bestD[k] = dO;
                bestT[k] = tO;
            }
        }
    }

    if (chunk == 0) {
        #pragma unroll
        for (int k = 0; k < 4; ++k) {
            const int g = pbase + grp * 4 + k;
            const int t = bestT[k];
            const float px = sp[(grp * 4 + k) * 3 + 0];
            const float py = sp[(grp * 4 + k) * 3 + 1];
            const float pz = sp[(grp * 4 + k) * 3 + 2];
            const int r = region_of(px, py, pz,
                                    sm[0][t], sm[1][t], sm[2][t],
                                    sm[3][t], sm[4][t], sm[5][t],
                                    sm[6][t], sm[7][t], sm[8][t]);
            out[g]          = bestD[k];
            out[BN + g]     = (float)r;
            out[2 * BN + g] = (float)t;
        }
    }
}

extern "C" void kernel_launch(void* const* d_in, const int* in_sizes, int n_in,
                              void* d_out, int out_size)
{
    const float* xyz  = (const float*)d_in[0];
    const float* tri1 = (const float*)d_in[1];
    const float* tri2 = (const float*)d_in[2];
    const float* tri3 = (const float*)d_in[3];
    float* out = (float*)d_out;

    dim3 grid(BN / 16);   // 1024 CTAs
    dim3 block(128);
    tridist_kernel<<<grid, block>>>(xyz, tri1, tri2, tri3, out);
}